// round 12
// baseline (speedup 1.0000x reference)
#include <cuda_runtime.h>
#include <cstdint>

#define T_STEPS 4096
#define RES     2048
#define DIMS    64
#define NCTA    128
#define ROWS_PER_CTA 16   // RES / NCTA
#define THREADS_ESN  512
#define NGROUPS 1024      // RES/2 groups of {h0,h1,tag,pad}

// ---------------- scratch (static device globals; no runtime allocs) ----------------
__device__ float g_U[(size_t)T_STEPS * DIMS];        // [t][d]
__device__ float g_G[(size_t)T_STEPS * RES];         // [t][r]  (W_in @ u_t, TRANSPOSED)
__device__ float g_Yp[(size_t)T_STEPS * NCTA];       // [t][cta] partial dW_h . h
__device__ __align__(16) unsigned int g_buf[2][NGROUPS * 4];  // [parity][group*4] = {h0,h1,tag,pad}

// packed f32x2 FMA (Blackwell)
__device__ __forceinline__ unsigned long long ffma2(unsigned long long a,
                                                    unsigned long long b,
                                                    unsigned long long c) {
    unsigned long long d;
    asm("fma.rn.f32x2 %0, %1, %2, %3;" : "=l"(d) : "l"(a), "l"(b), "l"(c));
    return d;
}

// fast tanh: 1 - 2/(exp(2x)+1); 2 MUFU ops, rel err ~2e-7/step (budget 1e-3)
__device__ __forceinline__ float ftanh(float x) {
    float e = __expf(2.0f * x);
    return 1.0f - __fdividef(2.0f, e + 1.0f);
}

// ---------------- kernel 1: U[t][d] = C@x_t; also zero the exchange buffers ---------
__global__ __launch_bounds__(256) void k_u(const float* __restrict__ X,
                                           const float* __restrict__ C) {
    __shared__ float Cs[64][65];
    __shared__ float xs[4][64];
    int tid = threadIdx.x;
    int b = blockIdx.x;
    for (int i = tid; i < 64 * 64; i += 256) Cs[i >> 6][i & 63] = C[i];
    int tl = tid >> 6, d = tid & 63;
    int t = b * 4 + tl;
    xs[tl][d] = X[t * 64 + d];
    __syncthreads();
    float acc = 0.f;
#pragma unroll
    for (int i = 0; i < 64; i++) acc = fmaf(Cs[d][i], xs[tl][i], acc);
    g_U[t * 64 + d] = acc;
    // zero both parity buffers (2 * 1024 * 4 = 8192 ints) so stale tags never match
    int gi = b * 256 + tid;
    if (gi < 2 * NGROUPS * 4) ((unsigned int*)g_buf)[gi] = 0u;
}

// ---------------- kernel 2: G[t][r] = sum_d W_in[r][d] * U[t][d]  (transposed) ------
__global__ __launch_bounds__(512) void k_g(const float* __restrict__ Win) {
    __shared__ __align__(8) float Us[32][66];   // 66: rows stay 8B aligned for LDS.64
    int tid = threadIdx.x, w = tid >> 5, l = tid & 31;
    int t0 = blockIdx.x * 32;
    for (int i = tid; i < 32 * 64; i += 512) Us[i >> 6][i & 63] = g_U[t0 * 64 + i];
    __syncthreads();
    const unsigned long long* up = reinterpret_cast<const unsigned long long*>(&Us[l][0]);
    for (int k = 0; k < 128; k++) {
        int r = w * 128 + k;
        const ulonglong2* wp = reinterpret_cast<const ulonglong2*>(Win + r * 64);
        unsigned long long acc = 0ull;
#pragma unroll
        for (int j = 0; j < 16; j++) {
            ulonglong2 wv = __ldg(wp + j);   // 4 weights, broadcast across the warp
            acc = ffma2(wv.x, up[2 * j],     acc);
            acc = ffma2(wv.y, up[2 * j + 1], acc);
        }
        float s = __uint_as_float((unsigned)acc) +
                  __uint_as_float((unsigned)(acc >> 32));
        g_G[(size_t)(t0 + l) * RES + r] = s;  // [t][r]: one 64B line per CTA per step
    }
}

// ---------------- kernel 3: persistent reservoir recurrence -------------------------
// 128 CTAs x 512 threads. CTA c owns rows [16c, 16c+16) of W_res in registers.
// Protocol (proven): 16B tag-in-payload groups {h0,h1,tag=t+1,0}; done-flag polling;
// poll gated by a barrier. NEW: warps 0-7 each reduce a ROW PAIR (lanes 0-15: row 2w,
// lanes 16-31: row 2w+1) and lane 0 publishes its group DIRECTLY -- no hout smem
// round-trip, publishes issued before the poll-gating barrier.
__global__ __launch_bounds__(THREADS_ESN, 1) void k_esn(const float* __restrict__ Wres,
                                                        const float* __restrict__ dW) {
    __shared__ __align__(16) float hsm[RES];
    __shared__ float parts[16][17];
    __shared__ float ypp[8];

    int tid = threadIdx.x, w = tid >> 5, l = tid & 31;
    int cta = blockIdx.x;
    int row = l >> 1, half = l & 1;
    int grow = cta * ROWS_PER_CTA + row;     // global row this lane accumulates
    int prow = 2 * w + (l >> 4);             // row-in-CTA this lane reduces (warps 0-7)

    // Load this lane's 64 W_res weights as 32 packed f32x2 operands.
    unsigned long long wreg[32];
    {
        const ulonglong2* wp = reinterpret_cast<const ulonglong2*>(
            Wres + (size_t)grow * RES + w * 128 + half * 4);
#pragma unroll
        for (int j = 0; j < 16; j++) {
            ulonglong2 v = wp[j * 2];        // 16B at float offset j*8
            wreg[2 * j]     = v.x;
            wreg[2 * j + 1] = v.y;
        }
    }

    // warps 0-7 lane 0: the two readout weights for this warp's row pair
    float dw0 = 0.f, dw1 = 0.f;
    if (w < 8) {
        dw0 = __ldg(dW + 64 + cta * ROWS_PER_CTA + 2 * w);
        dw1 = __ldg(dW + 64 + cta * ROWS_PER_CTA + 2 * w + 1);
    }

    for (int i = tid; i < RES; i += THREADS_ESN) hsm[i] = 0.f;
    __syncthreads();

    for (int t = 0; t < T_STEPS; t++) {
        // warps 0-7 prefetch G for their reduce row (one 64B line CTA-wide)
        float gval = (w < 8) ? __ldg(&g_G[(size_t)t * RES + cta * ROWS_PER_CTA + prow]) : 0.f;

        // partial dot over this lane's 64 columns (packed f32x2)
        const ulonglong2* hp = reinterpret_cast<const ulonglong2*>(
            hsm + w * 128 + half * 4);
        unsigned long long acc0 = 0ull, acc1 = 0ull;
#pragma unroll
        for (int j = 0; j < 16; j++) {
            ulonglong2 hv = hp[j * 2];       // LDS.128, 2 distinct addrs/warp: conflict-free
            acc0 = ffma2(wreg[2 * j],     hv.x, acc0);
            acc1 = ffma2(wreg[2 * j + 1], hv.y, acc1);
        }
        float s = __uint_as_float((unsigned)acc0) +
                  __uint_as_float((unsigned)(acc0 >> 32)) +
                  __uint_as_float((unsigned)acc1) +
                  __uint_as_float((unsigned)(acc1 >> 32));
        s += __shfl_xor_sync(0xffffffffu, s, 1);        // combine the two halves
        if (half == 0) parts[row][w] = s;
        __syncthreads();                                 // bar1: parts ready

        unsigned int* bufp = g_buf[t & 1];

        // ---- warps 0-7: reduce row pair, tanh, publish directly from lane 0 -------
        if (w < 8) {
            float v = parts[prow][l & 15];               // 16 partials for this row
            v += __shfl_xor_sync(0xffffffffu, v, 8);     // butterfly within 16-lane half
            v += __shfl_xor_sync(0xffffffffu, v, 4);
            v += __shfl_xor_sync(0xffffffffu, v, 2);
            v += __shfl_xor_sync(0xffffffffu, v, 1);
            float hv = ftanh(v + gval);                  // lanes 0-15: h_{2w}; 16-31: h_{2w+1}
            float h1 = __shfl_sync(0xffffffffu, hv, 16);
            if (l == 0) {
                unsigned int* p = bufp + (size_t)(cta * 8 + w) * 4;
                asm volatile("st.global.cg.v4.u32 [%0], {%1,%2,%3,%4};"
                             :: "l"(p), "r"(__float_as_uint(hv)), "r"(__float_as_uint(h1)),
                                "r"((unsigned int)(t + 1)), "r"(0u) : "memory");
                ypp[w] = dw0 * hv + dw1 * h1;            // readout partial, off-path
            }
        }
        __syncthreads();                                 // bar2: publishes issued; gate polls

        // warp 8 lane 0: deterministic fixed-order readout sum (off critical path)
        if (tid == 256) {
            float y = ((ypp[0] + ypp[1]) + (ypp[2] + ypp[3])) +
                      ((ypp[4] + ypp[5]) + (ypp[6] + ypp[7]));
            g_Yp[(size_t)t * NCTA + cta] = y;
        }

        // ---- consume: poll 2 groups per thread until tag == t+1, scatter to smem --
        if (t + 1 < T_STEPS) {
            unsigned int tag = (unsigned int)(t + 1);
            const unsigned int* p0 = bufp + (size_t)tid * 4;
            const unsigned int* p1 = bufp + (size_t)(tid + 512) * 4;
            unsigned int a0, a1, a2, a3, b0, b1, b2, b3;
            bool d0 = false, d1 = false;
            do {
                if (!d0) {
                    asm volatile("ld.global.cg.v4.u32 {%0,%1,%2,%3},[%4];"
                                 : "=r"(a0), "=r"(a1), "=r"(a2), "=r"(a3) : "l"(p0));
                    d0 = (a2 == tag);
                }
                if (!d1) {
                    asm volatile("ld.global.cg.v4.u32 {%0,%1,%2,%3},[%4];"
                                 : "=r"(b0), "=r"(b1), "=r"(b2), "=r"(b3) : "l"(p1));
                    d1 = (b2 == tag);
                }
            } while (!(d0 && d1));
            // group g holds h[2g], h[2g+1]
            *reinterpret_cast<float2*>(hsm + 2 * tid) =
                make_float2(__uint_as_float(a0), __uint_as_float(a1));
            *reinterpret_cast<float2*>(hsm + 1024 + 2 * tid) =
                make_float2(__uint_as_float(b0), __uint_as_float(b1));
            __syncthreads();                             // bar3: hsm ready
        }
    }
}

// ---------------- kernel 4: y[t] = dW[0:64].U[t] + sum_c Yp[t][c] + b ---------------
__global__ __launch_bounds__(256) void k_out(const float* __restrict__ dW,
                                             const float* __restrict__ db,
                                             float* __restrict__ y) {
    int tid = threadIdx.x, w = tid >> 5, l = tid & 31;
    int t = blockIdx.x * 8 + w;
    const float* up = g_U + (size_t)t * DIMS;
    const float* pp = g_Yp + (size_t)t * NCTA;
    float acc = dW[l] * up[l] + dW[32 + l] * up[32 + l];
    acc += pp[l] + pp[32 + l] + pp[64 + l] + pp[96 + l];
#pragma unroll
    for (int o = 16; o; o >>= 1) acc += __shfl_xor_sync(0xffffffffu, acc, o);
    if (l == 0) y[t] = acc + db[0];
}

// ---------------- launcher ----------------------------------------------------------
extern "C" void kernel_launch(void* const* d_in, const int* in_sizes, int n_in,
                              void* d_out, int out_size) {
    const float* X    = (const float*)d_in[0];   // (4096, 64, 1)
    const float* C    = (const float*)d_in[1];   // (64, 64)
    const float* Win  = (const float*)d_in[2];   // (2048, 64)
    const float* Wres = (const float*)d_in[3];   // (2048, 2048)
    const float* dW   = (const float*)d_in[4];   // (1, 2112)
    const float* db   = (const float*)d_in[5];   // (1,)
    float* y = (float*)d_out;                    // (4096, 1, 1)

    k_u  <<<T_STEPS / 4, 256>>>(X, C);           // also zeroes g_buf tags
    k_g  <<<T_STEPS / 32, 512>>>(Win);
    k_esn<<<NCTA, THREADS_ESN>>>(Wres, dW);
    k_out<<<T_STEPS / 8, 256>>>(dW, db, y);
}

// round 13
// speedup vs baseline: 1.3413x; 1.3413x over previous
#include <cuda_runtime.h>
#include <cstdint>

#define T_STEPS 4096
#define RES     2048
#define DIMS    64
#define NCTA    128
#define ROWS_PER_CTA 16   // RES / NCTA
#define THREADS_ESN  512
#define NGROUPS 1024      // RES/2 groups of {h0,h1,tag,pad}

// ---------------- scratch (static device globals; no runtime allocs) ----------------
__device__ float g_U[(size_t)T_STEPS * DIMS];        // [t][d]
__device__ float g_G[(size_t)T_STEPS * RES];         // [t][r]  (W_in @ u_t, TRANSPOSED)
__device__ float g_Yp[(size_t)T_STEPS * NCTA];       // [t][cta] partial dW_h . h
__device__ __align__(16) unsigned int g_buf[2][NGROUPS * 4];  // [parity][group*4] = {h0,h1,tag,pad}

// packed f32x2 FMA (Blackwell)
__device__ __forceinline__ unsigned long long ffma2(unsigned long long a,
                                                    unsigned long long b,
                                                    unsigned long long c) {
    unsigned long long d;
    asm("fma.rn.f32x2 %0, %1, %2, %3;" : "=l"(d) : "l"(a), "l"(b), "l"(c));
    return d;
}

// fast tanh: 1 - 2/(exp(2x)+1); 2 MUFU ops, rel err ~2e-7/step (budget 1e-3)
__device__ __forceinline__ float ftanh(float x) {
    float e = __expf(2.0f * x);
    return 1.0f - __fdividef(2.0f, e + 1.0f);
}

// ---------------- kernel 1: U[t][d] = C@x_t; also zero the exchange buffers ---------
__global__ __launch_bounds__(256) void k_u(const float* __restrict__ X,
                                           const float* __restrict__ C) {
    __shared__ float Cs[64][65];
    __shared__ float xs[4][64];
    int tid = threadIdx.x;
    int b = blockIdx.x;
    for (int i = tid; i < 64 * 64; i += 256) Cs[i >> 6][i & 63] = C[i];
    int tl = tid >> 6, d = tid & 63;
    int t = b * 4 + tl;
    xs[tl][d] = X[t * 64 + d];
    __syncthreads();
    float acc = 0.f;
#pragma unroll
    for (int i = 0; i < 64; i++) acc = fmaf(Cs[d][i], xs[tl][i], acc);
    g_U[t * 64 + d] = acc;
    // zero both parity buffers (2 * 1024 * 4 = 8192 ints) so stale tags never match
    int gi = b * 256 + tid;
    if (gi < 2 * NGROUPS * 4) ((unsigned int*)g_buf)[gi] = 0u;
}

// ---------------- kernel 2: G[t][r] = sum_d W_in[r][d] * U[t][d]  (transposed) ------
__global__ __launch_bounds__(512) void k_g(const float* __restrict__ Win) {
    __shared__ __align__(8) float Us[32][66];   // 66: rows stay 8B aligned for LDS.64
    int tid = threadIdx.x, w = tid >> 5, l = tid & 31;
    int t0 = blockIdx.x * 32;
    for (int i = tid; i < 32 * 64; i += 512) Us[i >> 6][i & 63] = g_U[t0 * 64 + i];
    __syncthreads();
    const unsigned long long* up = reinterpret_cast<const unsigned long long*>(&Us[l][0]);
    for (int k = 0; k < 128; k++) {
        int r = w * 128 + k;
        const ulonglong2* wp = reinterpret_cast<const ulonglong2*>(Win + r * 64);
        unsigned long long acc = 0ull;
#pragma unroll
        for (int j = 0; j < 16; j++) {
            ulonglong2 wv = __ldg(wp + j);   // 4 weights, broadcast across the warp
            acc = ffma2(wv.x, up[2 * j],     acc);
            acc = ffma2(wv.y, up[2 * j + 1], acc);
        }
        float s = __uint_as_float((unsigned)acc) +
                  __uint_as_float((unsigned)(acc >> 32));
        g_G[(size_t)(t0 + l) * RES + r] = s;  // [t][r]: one 64B line per CTA per step
    }
}

// ---------------- kernel 3: persistent reservoir recurrence (R11 structure) ---------
// 128 CTAs x 512 threads. CTA c owns rows [16c, 16c+16) of W_res in registers.
// Cross-CTA sync: tag-in-payload. Producer stores {h0,h1,tag=t+1,0} as STG.128;
// consumers poll the 16B group itself (tag visible => data visible; no fences).
// Consume remap: thread tid polls ADJACENT groups 2*tid, 2*tid+1 (same 32B sector)
// and scatters with ONE float4 STS at hsm+4*tid.
__global__ __launch_bounds__(THREADS_ESN, 1) void k_esn(const float* __restrict__ Wres,
                                                        const float* __restrict__ dW) {
    __shared__ __align__(16) float hsm[RES];
    __shared__ float parts[16][17];
    __shared__ __align__(16) float hout[16];

    int tid = threadIdx.x, w = tid >> 5, l = tid & 31;
    int cta = blockIdx.x;
    int row = l >> 1, half = l & 1;
    int grow = cta * ROWS_PER_CTA + row;     // global row this lane accumulates
    int outrow = cta * ROWS_PER_CTA + w;     // global row this warp outputs

    // Load this lane's 64 W_res weights as 32 packed f32x2 operands.
    unsigned long long wreg[32];
    {
        const ulonglong2* wp = reinterpret_cast<const ulonglong2*>(
            Wres + (size_t)grow * RES + w * 128 + half * 4);
#pragma unroll
        for (int j = 0; j < 16; j++) {
            ulonglong2 v = wp[j * 2];        // 16B at float offset j*8
            wreg[2 * j]     = v.x;
            wreg[2 * j + 1] = v.y;
        }
    }

    // warp 1 lane 0 keeps the CTA's 16 readout weights dW[64 + cta*16 + j] in regs
    float dwreg[16];
    if (tid == 32) {
#pragma unroll
        for (int j = 0; j < 16; j++) dwreg[j] = __ldg(dW + 64 + cta * ROWS_PER_CTA + j);
    }

    for (int i = tid; i < RES; i += THREADS_ESN) hsm[i] = 0.f;
    __syncthreads();

    for (int t = 0; t < T_STEPS; t++) {
        // prefetch this warp's G value early (independent of h); 16 warps share 1 line
        float gval = (l == 0) ? __ldg(&g_G[(size_t)t * RES + outrow]) : 0.f;

        // partial dot over this lane's 64 columns (packed f32x2)
        const ulonglong2* hp = reinterpret_cast<const ulonglong2*>(
            hsm + w * 128 + half * 4);
        unsigned long long acc0 = 0ull, acc1 = 0ull;
#pragma unroll
        for (int j = 0; j < 16; j++) {
            ulonglong2 hv = hp[j * 2];       // LDS.128, 2 distinct addrs/warp: conflict-free
            acc0 = ffma2(wreg[2 * j],     hv.x, acc0);
            acc1 = ffma2(wreg[2 * j + 1], hv.y, acc1);
        }
        float s = __uint_as_float((unsigned)acc0) +
                  __uint_as_float((unsigned)(acc0 >> 32)) +
                  __uint_as_float((unsigned)acc1) +
                  __uint_as_float((unsigned)(acc1 >> 32));
        s += __shfl_xor_sync(0xffffffffu, s, 1);        // combine the two halves
        if (half == 0) parts[row][w] = s;
        __syncthreads();

        // warp w reduces row w: lanes 0-7 fold 16 partials to 8, then 3 shfls
        float v = 0.f;
        if (l < 8) v = parts[w][l] + parts[w][l + 8];
        v += __shfl_xor_sync(0xffffffffu, v, 4);
        v += __shfl_xor_sync(0xffffffffu, v, 2);
        v += __shfl_xor_sync(0xffffffffu, v, 1);
        if (l == 0) hout[w] = ftanh(v + gval);
        __syncthreads();

        // ---- publish: 8 tagged 16B groups {h_{2j}, h_{2j+1}, t+1, 0} (warp 0) -----
        unsigned int* bufp = g_buf[t & 1];
        if (tid < 8) {
            float2 hv = *reinterpret_cast<const float2*>(&hout[2 * tid]);
            unsigned int* p = bufp + (size_t)(cta * 8 + tid) * 4;
            asm volatile("st.global.cg.v4.u32 [%0], {%1,%2,%3,%4};"
                         :: "l"(p), "r"(__float_as_uint(hv.x)), "r"(__float_as_uint(hv.y)),
                            "r"((unsigned int)(t + 1)), "r"(0u) : "memory");
        }
        // warp 1 lane 0: per-CTA readout partial (deterministic fixed-order sum)
        if (tid == 32) {
            float y0 = 0.f, y1 = 0.f, y2 = 0.f, y3 = 0.f;
#pragma unroll
            for (int j = 0; j < 4; j++) {
                y0 = fmaf(dwreg[4 * j + 0], hout[4 * j + 0], y0);
                y1 = fmaf(dwreg[4 * j + 1], hout[4 * j + 1], y1);
                y2 = fmaf(dwreg[4 * j + 2], hout[4 * j + 2], y2);
                y3 = fmaf(dwreg[4 * j + 3], hout[4 * j + 3], y3);
            }
            g_Yp[(size_t)t * NCTA + cta] = (y0 + y1) + (y2 + y3);
        }

        // ---- consume: poll ADJACENT groups 2*tid, 2*tid+1 (one 32B sector), then
        //      scatter h[4*tid..4*tid+4) with a single float4 STS ------------------
        if (t + 1 < T_STEPS) {
            unsigned int tag = (unsigned int)(t + 1);
            const unsigned int* p0 = bufp + (size_t)(2 * tid) * 4;
            const unsigned int* p1 = p0 + 4;
            unsigned int a0, a1, a2, a3, b0, b1, b2, b3;
            bool d0 = false, d1 = false;
            do {
                if (!d0) {
                    asm volatile("ld.global.cg.v4.u32 {%0,%1,%2,%3},[%4];"
                                 : "=r"(a0), "=r"(a1), "=r"(a2), "=r"(a3) : "l"(p0));
                    d0 = (a2 == tag);
                }
                if (!d1) {
                    asm volatile("ld.global.cg.v4.u32 {%0,%1,%2,%3},[%4];"
                                 : "=r"(b0), "=r"(b1), "=r"(b2), "=r"(b3) : "l"(p1));
                    d1 = (b2 == tag);
                }
            } while (!(d0 && d1));
            // groups 2*tid, 2*tid+1 hold h[4*tid .. 4*tid+3]
            *reinterpret_cast<float4*>(hsm + 4 * tid) =
                make_float4(__uint_as_float(a0), __uint_as_float(a1),
                            __uint_as_float(b0), __uint_as_float(b1));
            __syncthreads();
        }
    }
}

// ---------------- kernel 4: y[t] = dW[0:64].U[t] + sum_c Yp[t][c] + b ---------------
// warp per t: 64 U terms (2/lane) + 128 partials (4/lane), butterfly reduce.
__global__ __launch_bounds__(256) void k_out(const float* __restrict__ dW,
                                             const float* __restrict__ db,
                                             float* __restrict__ y) {
    int tid = threadIdx.x, w = tid >> 5, l = tid & 31;
    int t = blockIdx.x * 8 + w;
    const float* up = g_U + (size_t)t * DIMS;
    const float* pp = g_Yp + (size_t)t * NCTA;
    float acc = dW[l] * up[l] + dW[32 + l] * up[32 + l];
    acc += pp[l] + pp[32 + l] + pp[64 + l] + pp[96 + l];
#pragma unroll
    for (int o = 16; o; o >>= 1) acc += __shfl_xor_sync(0xffffffffu, acc, o);
    if (l == 0) y[t] = acc + db[0];
}

// ---------------- launcher ----------------------------------------------------------
extern "C" void kernel_launch(void* const* d_in, const int* in_sizes, int n_in,
                              void* d_out, int out_size) {
    const float* X    = (const float*)d_in[0];   // (4096, 64, 1)
    const float* C    = (const float*)d_in[1];   // (64, 64)
    const float* Win  = (const float*)d_in[2];   // (2048, 64)
    const float* Wres = (const float*)d_in[3];   // (2048, 2048)
    const float* dW   = (const float*)d_in[4];   // (1, 2112)
    const float* db   = (const float*)d_in[5];   // (1,)
    float* y = (float*)d_out;                    // (4096, 1, 1)

    k_u  <<<T_STEPS / 4, 256>>>(X, C);           // also zeroes g_buf tags
    k_g  <<<T_STEPS / 32, 512>>>(Win);
    k_esn<<<NCTA, THREADS_ESN>>>(Wres, dW);
    k_out<<<T_STEPS / 8, 256>>>(dW, db, y);
}

// round 14
// speedup vs baseline: 1.5272x; 1.1386x over previous
#include <cuda_runtime.h>
#include <cstdint>

#define T_STEPS 4096
#define RES     2048
#define DIMS    64
#define NCTA    128
#define ROWS_PER_CTA 16   // RES / NCTA
#define THREADS_ESN  512
#define NGROUPS 1024      // RES/2 groups of {h0,h1,tag,pad}

// ---------------- scratch (static device globals; no runtime allocs) ----------------
__device__ float g_U[(size_t)T_STEPS * DIMS];        // [t][d]
__device__ float g_G[(size_t)T_STEPS * RES];         // [t][r]  (W_in @ u_t, TRANSPOSED)
__device__ float g_Yp[(size_t)T_STEPS * NCTA];       // [t][cta] partial dW_h . h
__device__ __align__(16) unsigned int g_buf[2][NGROUPS * 4];  // [parity][group*4] = {h0,h1,tag,pad}

// packed f32x2 FMA (Blackwell)
__device__ __forceinline__ unsigned long long ffma2(unsigned long long a,
                                                    unsigned long long b,
                                                    unsigned long long c) {
    unsigned long long d;
    asm("fma.rn.f32x2 %0, %1, %2, %3;" : "=l"(d) : "l"(a), "l"(b), "l"(c));
    return d;
}

// fast tanh: 1 - 2/(exp(2x)+1); 2 MUFU ops, rel err ~2e-7/step (budget 1e-3)
__device__ __forceinline__ float ftanh(float x) {
    float e = __expf(2.0f * x);
    return 1.0f - __fdividef(2.0f, e + 1.0f);
}

// ---------------- kernel 1: U[t][d] = C@x_t; also zero the exchange buffers ---------
__global__ __launch_bounds__(256) void k_u(const float* __restrict__ X,
                                           const float* __restrict__ C) {
    __shared__ float Cs[64][65];
    __shared__ float xs[4][64];
    int tid = threadIdx.x;
    int b = blockIdx.x;
    for (int i = tid; i < 64 * 64; i += 256) Cs[i >> 6][i & 63] = C[i];
    int tl = tid >> 6, d = tid & 63;
    int t = b * 4 + tl;
    xs[tl][d] = X[t * 64 + d];
    __syncthreads();
    float acc = 0.f;
#pragma unroll
    for (int i = 0; i < 64; i++) acc = fmaf(Cs[d][i], xs[tl][i], acc);
    g_U[t * 64 + d] = acc;
    // zero both parity buffers (2 * 1024 * 4 = 8192 ints) so stale tags never match
    int gi = b * 256 + tid;
    if (gi < 2 * NGROUPS * 4) ((unsigned int*)g_buf)[gi] = 0u;
}

// ---------------- kernel 2: G[t][r] = sum_d W_in[r][d] * U[t][d]  (transposed) ------
__global__ __launch_bounds__(512) void k_g(const float* __restrict__ Win) {
    __shared__ __align__(8) float Us[32][66];   // 66: rows stay 8B aligned for LDS.64
    int tid = threadIdx.x, w = tid >> 5, l = tid & 31;
    int t0 = blockIdx.x * 32;
    for (int i = tid; i < 32 * 64; i += 512) Us[i >> 6][i & 63] = g_U[t0 * 64 + i];
    __syncthreads();
    const unsigned long long* up = reinterpret_cast<const unsigned long long*>(&Us[l][0]);
    for (int k = 0; k < 128; k++) {
        int r = w * 128 + k;
        const ulonglong2* wp = reinterpret_cast<const ulonglong2*>(Win + r * 64);
        unsigned long long acc = 0ull;
#pragma unroll
        for (int j = 0; j < 16; j++) {
            ulonglong2 wv = __ldg(wp + j);   // 4 weights, broadcast across the warp
            acc = ffma2(wv.x, up[2 * j],     acc);
            acc = ffma2(wv.y, up[2 * j + 1], acc);
        }
        float s = __uint_as_float((unsigned)acc) +
                  __uint_as_float((unsigned)(acc >> 32));
        g_G[(size_t)(t0 + l) * RES + r] = s;  // [t][r]: one 64B line per CTA per step
    }
}

// ---------------- kernel 3: persistent reservoir recurrence (validated optimum) -----
// 128 CTAs x 512 threads. CTA c owns rows [16c, 16c+16) of W_res in registers.
// Cross-CTA sync: tag-in-payload. Producer stores {h0,h1,tag=t+1,0} as STG.128;
// consumers poll the 16B group itself (tag visible => data visible; no fences).
__global__ __launch_bounds__(THREADS_ESN, 1) void k_esn(const float* __restrict__ Wres,
                                                        const float* __restrict__ dW) {
    __shared__ __align__(16) float hsm[RES];
    __shared__ float parts[16][17];
    __shared__ __align__(16) float hout[16];

    int tid = threadIdx.x, w = tid >> 5, l = tid & 31;
    int cta = blockIdx.x;
    int row = l >> 1, half = l & 1;
    int grow = cta * ROWS_PER_CTA + row;     // global row this lane accumulates
    int outrow = cta * ROWS_PER_CTA + w;     // global row this warp outputs

    // Load this lane's 64 W_res weights as 32 packed f32x2 operands.
    unsigned long long wreg[32];
    {
        const ulonglong2* wp = reinterpret_cast<const ulonglong2*>(
            Wres + (size_t)grow * RES + w * 128 + half * 4);
#pragma unroll
        for (int j = 0; j < 16; j++) {
            ulonglong2 v = wp[j * 2];        // 16B at float offset j*8
            wreg[2 * j]     = v.x;
            wreg[2 * j + 1] = v.y;
        }
    }

    // warp 1 lane 0 keeps the CTA's 16 readout weights dW[64 + cta*16 + j] in regs
    float dwreg[16];
    if (tid == 32) {
#pragma unroll
        for (int j = 0; j < 16; j++) dwreg[j] = __ldg(dW + 64 + cta * ROWS_PER_CTA + j);
    }

    for (int i = tid; i < RES; i += THREADS_ESN) hsm[i] = 0.f;
    __syncthreads();

    for (int t = 0; t < T_STEPS; t++) {
        // prefetch this warp's G value early (independent of h); 16 warps share 1 line
        float gval = (l == 0) ? __ldg(&g_G[(size_t)t * RES + outrow]) : 0.f;

        // partial dot over this lane's 64 columns (packed f32x2)
        const ulonglong2* hp = reinterpret_cast<const ulonglong2*>(
            hsm + w * 128 + half * 4);
        unsigned long long acc0 = 0ull, acc1 = 0ull;
#pragma unroll
        for (int j = 0; j < 16; j++) {
            ulonglong2 hv = hp[j * 2];       // LDS.128, 2 distinct addrs/warp: conflict-free
            acc0 = ffma2(wreg[2 * j],     hv.x, acc0);
            acc1 = ffma2(wreg[2 * j + 1], hv.y, acc1);
        }
        float s = __uint_as_float((unsigned)acc0) +
                  __uint_as_float((unsigned)(acc0 >> 32)) +
                  __uint_as_float((unsigned)acc1) +
                  __uint_as_float((unsigned)(acc1 >> 32));
        s += __shfl_xor_sync(0xffffffffu, s, 1);        // combine the two halves
        if (half == 0) parts[row][w] = s;
        __syncthreads();

        // warp w reduces row w: lanes 0-7 fold 16 partials to 8, then 3 shfls
        float v = 0.f;
        if (l < 8) v = parts[w][l] + parts[w][l + 8];
        v += __shfl_xor_sync(0xffffffffu, v, 4);
        v += __shfl_xor_sync(0xffffffffu, v, 2);
        v += __shfl_xor_sync(0xffffffffu, v, 1);
        if (l == 0) hout[w] = ftanh(v + gval);
        __syncthreads();

        // ---- publish: 8 tagged 16B groups {h_{2j}, h_{2j+1}, t+1, 0} (warp 0) -----
        unsigned int* bufp = g_buf[t & 1];
        if (tid < 8) {
            float2 hv = *reinterpret_cast<const float2*>(&hout[2 * tid]);
            unsigned int* p = bufp + (size_t)(cta * 8 + tid) * 4;
            asm volatile("st.global.cg.v4.u32 [%0], {%1,%2,%3,%4};"
                         :: "l"(p), "r"(__float_as_uint(hv.x)), "r"(__float_as_uint(hv.y)),
                            "r"((unsigned int)(t + 1)), "r"(0u) : "memory");
        }
        // warp 1 lane 0: per-CTA readout partial (deterministic fixed-order sum)
        if (tid == 32) {
            float y0 = 0.f, y1 = 0.f, y2 = 0.f, y3 = 0.f;
#pragma unroll
            for (int j = 0; j < 4; j++) {
                y0 = fmaf(dwreg[4 * j + 0], hout[4 * j + 0], y0);
                y1 = fmaf(dwreg[4 * j + 1], hout[4 * j + 1], y1);
                y2 = fmaf(dwreg[4 * j + 2], hout[4 * j + 2], y2);
                y3 = fmaf(dwreg[4 * j + 3], hout[4 * j + 3], y3);
            }
            g_Yp[(size_t)t * NCTA + cta] = (y0 + y1) + (y2 + y3);
        }

        // ---- consume: poll 2 groups per thread until tag == t+1, scatter to smem --
        if (t + 1 < T_STEPS) {
            unsigned int tag = (unsigned int)(t + 1);
            const unsigned int* p0 = bufp + (size_t)tid * 4;
            const unsigned int* p1 = bufp + (size_t)(tid + 512) * 4;
            unsigned int a0, a1, a2, a3, b0, b1, b2, b3;
            bool d0 = false, d1 = false;
            do {
                if (!d0) {
                    asm volatile("ld.global.cg.v4.u32 {%0,%1,%2,%3},[%4];"
                                 : "=r"(a0), "=r"(a1), "=r"(a2), "=r"(a3) : "l"(p0));
                    d0 = (a2 == tag);
                }
                if (!d1) {
                    asm volatile("ld.global.cg.v4.u32 {%0,%1,%2,%3},[%4];"
                                 : "=r"(b0), "=r"(b1), "=r"(b2), "=r"(b3) : "l"(p1));
                    d1 = (b2 == tag);
                }
            } while (!(d0 && d1));
            // group g holds h[2g], h[2g+1]
            *reinterpret_cast<float2*>(hsm + 2 * tid) =
                make_float2(__uint_as_float(a0), __uint_as_float(a1));
            *reinterpret_cast<float2*>(hsm + 1024 + 2 * tid) =
                make_float2(__uint_as_float(b0), __uint_as_float(b1));
            __syncthreads();
        }
    }
}

// ---------------- kernel 4: y[t] = dW[0:64].U[t] + sum_c Yp[t][c] + b ---------------
// warp per t: 64 U terms (2/lane) + 128 partials (4/lane), butterfly reduce.
__global__ __launch_bounds__(256) void k_out(const float* __restrict__ dW,
                                             const float* __restrict__ db,
                                             float* __restrict__ y) {
    int tid = threadIdx.x, w = tid >> 5, l = tid & 31;
    int t = blockIdx.x * 8 + w;
    const float* up = g_U + (size_t)t * DIMS;
    const float* pp = g_Yp + (size_t)t * NCTA;
    float acc = dW[l] * up[l] + dW[32 + l] * up[32 + l];
    acc += pp[l] + pp[32 + l] + pp[64 + l] + pp[96 + l];
#pragma unroll
    for (int o = 16; o; o >>= 1) acc += __shfl_xor_sync(0xffffffffu, acc, o);
    if (l == 0) y[t] = acc + db[0];
}

// ---------------- launcher ----------------------------------------------------------
extern "C" void kernel_launch(void* const* d_in, const int* in_sizes, int n_in,
                              void* d_out, int out_size) {
    const float* X    = (const float*)d_in[0];   // (4096, 64, 1)
    const float* C    = (const float*)d_in[1];   // (64, 64)
    const float* Win  = (const float*)d_in[2];   // (2048, 64)
    const float* Wres = (const float*)d_in[3];   // (2048, 2048)
    const float* dW   = (const float*)d_in[4];   // (1, 2112)
    const float* db   = (const float*)d_in[5];   // (1,)
    float* y = (float*)d_out;                    // (4096, 1, 1)

    k_u  <<<T_STEPS / 4, 256>>>(X, C);           // also zeroes g_buf tags
    k_g  <<<T_STEPS / 32, 512>>>(Win);
    k_esn<<<NCTA, THREADS_ESN>>>(Wres, dW);
    k_out<<<T_STEPS / 8, 256>>>(dW, db, y);
}